// round 15
// baseline (speedup 1.0000x reference)
#include <cuda_runtime.h>
#include <cstdint>
#include <cstddef>

#define BATCH 65536
#define INF   770
#define XROW  1540
#define FTSZ  512
#define H1K   1024
#define NKT   25          // ft k-tiles of 32 (770 padded to 800)
#define TILE  4096        // floats per 128x32 frag-ordered B tile

// scratch (__device__ globals; referenced ONLY from device code)
__device__ float g_wf[4 * NKT * TILE];                 // ft_w frag tiles
__device__ float g_comb[(size_t)BATCH * H1K];          // crelu'd combined, row-major
__device__ int   g_bucket[BATCH];

__device__ __forceinline__ uint32_t smem_u32(const void* p) {
    uint32_t a;
    asm("{ .reg .u64 t; cvta.to.shared.u64 t, %1; cvt.u32.u64 %0, t; }" : "=r"(a) : "l"(p));
    return a;
}
__device__ __forceinline__ void cp16(uint32_t d, const void* s) {
    asm volatile("cp.async.cg.shared.global [%0], [%1], 16;" :: "r"(d), "l"(s));
}
__device__ __forceinline__ float tf32r(float v) {
    uint32_t r; asm("cvt.rna.tf32.f32 %0, %1;" : "=r"(r) : "f"(v));
    return __uint_as_float(r);
}
__device__ __forceinline__ void mma8(float& c0, float& c1, float& c2, float& c3,
                                     uint32_t a0, uint32_t a1, uint32_t a2, uint32_t a3,
                                     uint32_t b0, uint32_t b1) {
    asm volatile(
        "mma.sync.aligned.m16n8k8.row.col.f32.tf32.tf32.f32 "
        "{%0,%1,%2,%3},{%4,%5,%6,%7},{%8,%9},{%0,%1,%2,%3};"
        : "+f"(c0), "+f"(c1), "+f"(c2), "+f"(c3)
        : "r"(a0), "r"(a1), "r"(a2), "r"(a3), "r"(b0), "r"(b1));
}
__device__ __forceinline__ void fma2(unsigned long long& d, unsigned long long a,
                                     unsigned long long b) {
    asm("fma.rn.f32x2 %0, %1, %2, %0;" : "+l"(d) : "l"(a), "l"(b));
}

// ---- bucket ----
__global__ __launch_bounds__(256) void k_bucket(const float* __restrict__ x) {
    int row = blockIdx.x * 8 + (threadIdx.x >> 5);
    int lid = threadIdx.x & 31;
    const float4* xr = (const float4*)(x + (size_t)row * XROW);
    float s = 0.f;
#pragma unroll
    for (int j = 0; j < 6; j++) {
        float4 v = __ldg(xr + lid + j * 32);
        s += v.x + v.y + v.z + v.w;
    }
    for (int o = 16; o; o >>= 1) s += __shfl_xor_sync(0xffffffffu, s, o);
    if (lid == 0) {
        int bk = (int)(s * 8.0f / 33.0f);
        g_bucket[row] = bk < 0 ? 0 : (bk > 7 ? 7 : bk);
    }
}

// ---- stage ft_w: tf32 round + pad + B-frag permute ----
__global__ __launch_bounds__(256) void k_prep_wft(const float* __restrict__ w) {
    __shared__ float s[128][33];
    int kt = blockIdx.x, nblk = blockIdx.y;
    int tid = threadIdx.x;
#pragma unroll
    for (int i = 0; i < 16; i++) {
        int idx = tid + i * 256;
        int n = idx >> 5, k = idx & 31;
        int gk = kt * 32 + k;
        float v = (gk < INF) ? w[(size_t)(nblk * 128 + n) * INF + gk] : 0.f;
        s[n][k] = tf32r(v);
    }
    __syncthreads();
    float* dst = g_wf + ((size_t)nblk * NKT + kt) * TILE;
#pragma unroll
    for (int i = 0; i < 16; i++) {
        int d = tid + i * 256;
        int slot = d & 1, lane = (d >> 1) & 31, kc = (d >> 6) & 3, nt = d >> 8;
        int n = nt * 8 + (lane >> 2);
        int k = kc * 8 + slot * 4 + (lane & 3);
        dst[d] = s[n][k];
    }
}

// ---- FT GEMM: 128x128 CTA, warp 32x64; A fused from x via swizzled smem,
//      B cp.async 3-stage; ONE __syncthreads per ktile ----
// smem floats: A stages 2 x 4096 (row-major 32/row, k XOR (m&7)<<2), B 3 x 4096 = 80KB
__global__ __launch_bounds__(256, 2) void k_ft(const float* __restrict__ x,
                                               const float* __restrict__ ft_b) {
    extern __shared__ float sm[];
    int tid = threadIdx.x, wid = tid >> 5, lane = tid & 31;
    int side = blockIdx.x >> 2, nblk = blockIdx.x & 3, rb = blockIdx.y;
    int wm = wid & 3, wn = wid >> 2;

    const char* gB = (const char*)(g_wf + (size_t)nblk * NKT * TILE);
    uint32_t sbB = smem_u32(sm) + 8192 * 4;      // B region after 2 A stages

    // per-thread A slice: row am, k-half ak (16 floats per ktile)
    int am = tid >> 1, ak = (tid & 1) * 16;
    const float* xrow = x + (size_t)(rb * 128 + am) * XROW + side * INF;
    int aswz = (am & 7) << 2;

    float acc[64];
#pragma unroll
    for (int i = 0; i < 64; i++) acc[i] = 0.f;

    float a16[16];
    auto ldA = [&](int kt) {
        int k0 = kt * 32 + ak;
#pragma unroll
        for (int j = 0; j < 8; j++) {
            int gk = k0 + 2 * j;
            float2 v = (gk < INF) ? __ldg((const float2*)(xrow + gk))
                                  : make_float2(0.f, 0.f);
            a16[2 * j] = v.x; a16[2 * j + 1] = v.y;
        }
    };
    auto stsA = [&](int st) {
        float* base = sm + st * 4096 + am * 32;
#pragma unroll
        for (int q = 0; q < 4; q++) {
            int kb = ak + q * 4;
            float4 v;
            v.x = tf32r(a16[q * 4 + 0]);
            v.y = tf32r(a16[q * 4 + 1]);
            v.z = tf32r(a16[q * 4 + 2]);
            v.w = tf32r(a16[q * 4 + 3]);
            *(float4*)(base + (kb ^ aswz)) = v;
        }
    };
    auto issueB = [&](int kt, int st) {
        uint32_t d = sbB + st * 16384;
        const char* b = gB + (size_t)kt * 16384;
#pragma unroll
        for (int c = 0; c < 4; c++) {
            int idx = tid + c * 256;
            cp16(d + idx * 16, b + (size_t)idx * 16);
        }
        asm volatile("cp.async.commit_group;" ::: "memory");
    };

    // prologue
    ldA(0); stsA(0);
    ldA(1);                     // a16 holds ktile 1
    issueB(0, 0);
    issueB(1, 1);

    int rowbase = (wm * 32 + (lane >> 2)) * 32;
    int jl = lane & 3;
    int swz = (lane >> 2) << 2;

    for (int kt = 0; kt < NKT; kt++) {
        if (kt + 1 < NKT) asm volatile("cp.async.wait_group 1;" ::: "memory");
        else              asm volatile("cp.async.wait_group 0;" ::: "memory");
        __syncthreads();        // B[kt] + A stage kt&1 visible; prior readers done
        if (kt + 1 < NKT) stsA((kt + 1) & 1);     // stage last read in iter kt-1
        if (kt + 2 < NKT) { ldA(kt + 2); issueB(kt + 2, (kt + 2) % 3); }

        const float* sA = sm + (kt & 1) * 4096;
        const uint2* B = (const uint2*)(sm + 8192 + (kt % 3) * 4096);
#pragma unroll
        for (int kc = 0; kc < 4; kc++) {
            uint32_t a[2][4];
            uint2 b[8];
            int kx0 = (kc * 8 + jl) ^ swz;
            int kx4 = (kc * 8 + 4 + jl) ^ swz;
#pragma unroll
            for (int mt = 0; mt < 2; mt++) {
                const float* p = sA + rowbase + mt * 512;
                a[mt][0] = __float_as_uint(p[kx0]);
                a[mt][1] = __float_as_uint(p[256 + kx0]);
                a[mt][2] = __float_as_uint(p[kx4]);
                a[mt][3] = __float_as_uint(p[256 + kx4]);
            }
#pragma unroll
            for (int nt = 0; nt < 8; nt++)
                b[nt] = B[((wn * 8 + nt) * 4 + kc) * 32 + lane];
#pragma unroll
            for (int mt = 0; mt < 2; mt++)
#pragma unroll
                for (int nt = 0; nt < 8; nt++) {
                    float* c = acc + mt * 32 + nt * 4;
                    mma8(c[0], c[1], c[2], c[3],
                         a[mt][0], a[mt][1], a[mt][2], a[mt][3], b[nt].x, b[nt].y);
                }
        }
    }

    int r0 = rb * 128 + wm * 32 + (lane >> 2);
    int c0 = nblk * 128 + wn * 64 + 2 * (lane & 3);
#pragma unroll
    for (int mt = 0; mt < 2; mt++) {
#pragma unroll
        for (int nt = 0; nt < 8; nt++) {
            float* c = acc + mt * 32 + nt * 4;
            int col = c0 + nt * 8;
            float b0 = __ldg(ft_b + col), b1 = __ldg(ft_b + col + 1);
            float2 lo, hi;
            lo.x = fminf(fmaxf(c[0] + b0, 0.f), 1.f);
            lo.y = fminf(fmaxf(c[1] + b1, 0.f), 1.f);
            hi.x = fminf(fmaxf(c[2] + b0, 0.f), 1.f);
            hi.y = fminf(fmaxf(c[3] + b1, 0.f), 1.f);
            size_t base = (size_t)(r0 + mt * 16) * H1K + side * FTSZ + col;
            *(float2*)(g_comb + base) = lo;
            *(float2*)(g_comb + base + 8 * H1K) = hi;
        }
    }
}

// ---- head: CTA = 8 rows; packed f32x2 FMAs for the h1 layer ----
__global__ __launch_bounds__(256) void k_head(
    const float* __restrict__ h1_w, const float* __restrict__ h1_b,
    const float* __restrict__ h2_w, const float* __restrict__ h2_b,
    const float* __restrict__ h3_w, const float* __restrict__ h3_b,
    float* __restrict__ out) {
    __shared__ float scomb[8 * 1024];
    __shared__ float sh1[8][33];
    __shared__ int sbk[8];
    int tid = threadIdx.x, w = tid >> 5, lane = tid & 31;
    int blk = blockIdx.x;

    {
        const float4* src = (const float4*)(g_comb + (size_t)blk * 8 * H1K);
        float4* dst = (float4*)scomb;
#pragma unroll
        for (int i = 0; i < 8; i++) dst[tid + i * 256] = __ldg(src + tid + i * 256);
        if (tid < 8) sbk[tid] = g_bucket[blk * 8 + tid];
    }
    __syncthreads();

    unsigned long long acc2[4][8];
#pragma unroll
    for (int o = 0; o < 4; o++)
#pragma unroll
        for (int r = 0; r < 8; r++) acc2[o][r] = 0ull;

    for (int b = 0; b < 8; b++) {
        unsigned rm = 0;
#pragma unroll
        for (int r = 0; r < 8; r++) if (sbk[r] == b) rm |= 1u << r;
        if (!rm) continue;
        const float4* wb = (const float4*)(h1_w + ((size_t)b * 32 + w * 4) * H1K);
#pragma unroll
        for (int c = 0; c < 4; c++) {
            unsigned long long wp[4][4];
#pragma unroll
            for (int o = 0; o < 4; o++) {
                float4 w0 = __ldg(wb + o * 256 + c * 64 + lane);
                float4 w1 = __ldg(wb + o * 256 + c * 64 + 32 + lane);
                wp[o][0] = *(unsigned long long*)&w0.x;
                wp[o][1] = *(unsigned long long*)&w0.z;
                wp[o][2] = *(unsigned long long*)&w1.x;
                wp[o][3] = *(unsigned long long*)&w1.z;
            }
#pragma unroll
            for (int r = 0; r < 8; r++) {
                if (!((rm >> r) & 1)) continue;
                float4 c0 = *(const float4*)(scomb + r * 1024 + c * 256 + lane * 4);
                float4 c1 = *(const float4*)(scomb + r * 1024 + c * 256 + 128 + lane * 4);
                unsigned long long cp0 = *(unsigned long long*)&c0.x;
                unsigned long long cp1 = *(unsigned long long*)&c0.z;
                unsigned long long cp2 = *(unsigned long long*)&c1.x;
                unsigned long long cp3 = *(unsigned long long*)&c1.z;
#pragma unroll
                for (int o = 0; o < 4; o++) {
                    fma2(acc2[o][r], cp0, wp[o][0]);
                    fma2(acc2[o][r], cp1, wp[o][1]);
                    fma2(acc2[o][r], cp2, wp[o][2]);
                    fma2(acc2[o][r], cp3, wp[o][3]);
                }
            }
        }
    }

    float acc[4][8];
#pragma unroll
    for (int o = 0; o < 4; o++)
#pragma unroll
        for (int r = 0; r < 8; r++) {
            float2 p = *(float2*)&acc2[o][r];
            float s = p.x + p.y;
#pragma unroll
            for (int off = 16; off; off >>= 1) s += __shfl_xor_sync(0xffffffffu, s, off);
            acc[o][r] = s;
        }
    {
        int o = lane & 3, r = lane >> 2;
        int bk = sbk[r];
        float v = acc[o][r] + __ldg(h1_b + bk * 32 + w * 4 + o);
        sh1[r][w * 4 + o] = fminf(fmaxf(v, 0.f), 1.f);
    }
    __syncthreads();

    int row = blk * 8 + w;
    int bk = sbk[w];
    const float4* w2 = (const float4*)(h2_w + (size_t)bk * 1024 + lane * 32);
    float a = 0.f;
#pragma unroll
    for (int rr = 0; rr < 8; rr++) {
        float4 wv = __ldg(w2 + rr);
        const float* h = &sh1[w][rr * 4];
        a += wv.x * h[0] + wv.y * h[1] + wv.z * h[2] + wv.w * h[3];
    }
    float h2v = fminf(fmaxf(a + __ldg(h2_b + bk * 32 + lane), 0.f), 1.f);
    float v = __ldg(h3_w + bk * 32 + lane) * h2v;
#pragma unroll
    for (int off = 16; off; off >>= 1) v += __shfl_xor_sync(0xffffffffu, v, off);
    if (lane == 0) out[row] = v + __ldg(h3_b + bk);
}

extern "C" void kernel_launch(void* const* d_in, const int* in_sizes, int n_in,
                              void* d_out, int out_size) {
    const float* x    = (const float*)d_in[0];
    const float* ft_w = (const float*)d_in[1];
    const float* ft_b = (const float*)d_in[2];
    const float* h1_w = (const float*)d_in[3];
    const float* h1_b = (const float*)d_in[4];
    const float* h2_w = (const float*)d_in[5];
    const float* h2_b = (const float*)d_in[6];
    const float* h3_w = (const float*)d_in[7];
    const float* h3_b = (const float*)d_in[8];
    float* out = (float*)d_out;

    cudaFuncSetAttribute(k_ft, cudaFuncAttributeMaxDynamicSharedMemorySize, 81920);

    k_bucket<<<BATCH / 8, 256>>>(x);
    k_prep_wft<<<dim3(NKT, 4), 256>>>(ft_w);
    k_ft<<<dim3(8, 512), 256, 81920>>>(x, ft_b);
    k_head<<<BATCH / 8, 256>>>(h1_w, h1_b, h2_w, h2_b, h3_w, h3_b, out);
}

// round 16
// speedup vs baseline: 1.1831x; 1.1831x over previous
#include <cuda_runtime.h>
#include <cstdint>
#include <cstddef>

#define BATCH 65536
#define INF   770
#define XROW  1540
#define FTSZ  512
#define H1K   1024
#define NKT   25          // ft k-tiles of 32 (770 padded to 800)
#define TILE  4096        // floats per 128x32 frag-ordered tile

// scratch (__device__ globals; referenced ONLY from device code)
__device__ float g_xf[(size_t)2 * 512 * NKT * TILE];   // x: [side][rb][kt][4096]
__device__ float g_wf[4 * NKT * TILE];                 // ft_w frag tiles
__device__ float g_comb[(size_t)BATCH * H1K];          // crelu'd combined, row-major
__device__ int   g_bucket[BATCH];

__device__ __forceinline__ uint32_t smem_u32(const void* p) {
    uint32_t a;
    asm("{ .reg .u64 t; cvta.to.shared.u64 t, %1; cvt.u32.u64 %0, t; }" : "=r"(a) : "l"(p));
    return a;
}
__device__ __forceinline__ void cp16(uint32_t d, const void* s) {
    asm volatile("cp.async.cg.shared.global [%0], [%1], 16;" :: "r"(d), "l"(s));
}
__device__ __forceinline__ float tf32r(float v) {
    uint32_t r; asm("cvt.rna.tf32.f32 %0, %1;" : "=r"(r) : "f"(v));
    return __uint_as_float(r);
}
__device__ __forceinline__ void mma8(float& c0, float& c1, float& c2, float& c3,
                                     uint32_t a0, uint32_t a1, uint32_t a2, uint32_t a3,
                                     uint32_t b0, uint32_t b1) {
    asm volatile(
        "mma.sync.aligned.m16n8k8.row.col.f32.tf32.tf32.f32 "
        "{%0,%1,%2,%3},{%4,%5,%6,%7},{%8,%9},{%0,%1,%2,%3};"
        : "+f"(c0), "+f"(c1), "+f"(c2), "+f"(c3)
        : "r"(a0), "r"(a1), "r"(a2), "r"(a3), "r"(b0), "r"(b1));
}
__device__ __forceinline__ void fma2(unsigned long long& d, unsigned long long a,
                                     unsigned long long b) {
    asm("fma.rn.f32x2 %0, %1, %2, %0;" : "+l"(d) : "l"(a), "l"(b));
}

// ---- bucket ----
__global__ __launch_bounds__(256) void k_bucket(const float* __restrict__ x) {
    int row = blockIdx.x * 8 + (threadIdx.x >> 5);
    int lid = threadIdx.x & 31;
    const float4* xr = (const float4*)(x + (size_t)row * XROW);
    float s = 0.f;
#pragma unroll
    for (int j = 0; j < 6; j++) {
        float4 v = __ldg(xr + lid + j * 32);
        s += v.x + v.y + v.z + v.w;
    }
    for (int o = 16; o; o >>= 1) s += __shfl_xor_sync(0xffffffffu, s, o);
    if (lid == 0) {
        int bk = (int)(s * 8.0f / 33.0f);
        g_bucket[row] = bk < 0 ? 0 : (bk > 7 ? 7 : bk);
    }
}

// ---- stage x: tf32 round + pad + A-frag permute ----
__global__ __launch_bounds__(256) void k_prep_x(const float* __restrict__ x) {
    __shared__ float s[128][33];
    int kt = blockIdx.x, rb = blockIdx.y, side = blockIdx.z;
    int tid = threadIdx.x;
#pragma unroll
    for (int i = 0; i < 16; i++) {
        int idx = tid + i * 256;
        int m = idx >> 5, k = idx & 31;
        int gk = kt * 32 + k;
        float v = (gk < INF) ? x[((size_t)(rb * 128 + m)) * XROW + side * INF + gk] : 0.f;
        s[m][k] = tf32r(v);
    }
    __syncthreads();
    float* dst = g_xf + (((size_t)side * 512 + rb) * NKT + kt) * TILE;
#pragma unroll
    for (int i = 0; i < 16; i++) {
        int d = tid + i * 256;
        int slot = d & 3, lane = (d >> 2) & 31, kc = (d >> 7) & 3, mt = d >> 9;
        int m = mt * 16 + (slot & 1) * 8 + (lane >> 2);
        int k = kc * 8 + ((slot >> 1) & 1) * 4 + (lane & 3);
        dst[d] = s[m][k];
    }
}

// ---- stage ft_w: tf32 round + pad + B-frag permute ----
__global__ __launch_bounds__(256) void k_prep_wft(const float* __restrict__ w) {
    __shared__ float s[128][33];
    int kt = blockIdx.x, nblk = blockIdx.y;
    int tid = threadIdx.x;
#pragma unroll
    for (int i = 0; i < 16; i++) {
        int idx = tid + i * 256;
        int n = idx >> 5, k = idx & 31;
        int gk = kt * 32 + k;
        float v = (gk < INF) ? w[(size_t)(nblk * 128 + n) * INF + gk] : 0.f;
        s[n][k] = tf32r(v);
    }
    __syncthreads();
    float* dst = g_wf + ((size_t)nblk * NKT + kt) * TILE;
#pragma unroll
    for (int i = 0; i < 16; i++) {
        int d = tid + i * 256;
        int slot = d & 1, lane = (d >> 1) & 31, kc = (d >> 6) & 3, nt = d >> 8;
        int n = nt * 8 + (lane >> 2);
        int k = kc * 8 + slot * 4 + (lane & 3);
        dst[d] = s[n][k];
    }
}

// ---- FT GEMM: 128x128 CTA, warp 32x64, 3-stage pipeline, ONE sync/ktile ----
__global__ __launch_bounds__(256) void k_ft(const float* __restrict__ ft_b) {
    extern __shared__ float sm[];
    int tid = threadIdx.x, wid = tid >> 5, lane = tid & 31;
    int side = blockIdx.x >> 2, nblk = blockIdx.x & 3, rb = blockIdx.y;
    int wm = wid & 3, wn = wid >> 2;

    const char* gA = (const char*)(g_xf + ((size_t)side * 512 + rb) * NKT * TILE);
    const char* gB = (const char*)(g_wf + (size_t)nblk * NKT * TILE);
    uint32_t sb = smem_u32(sm);

    float acc[64];
#pragma unroll
    for (int i = 0; i < 64; i++) acc[i] = 0.f;

    auto issue = [&](int kt, int st) {
        uint32_t d = sb + st * 32768;
        const char* a = gA + (size_t)kt * 16384;
        const char* b = gB + (size_t)kt * 16384;
#pragma unroll
        for (int c = 0; c < 8; c++) {
            int idx = tid + c * 256;
            if (idx < 1024) cp16(d + idx * 16, a + (size_t)idx * 16);
            else            cp16(d + idx * 16, b + (size_t)(idx - 1024) * 16);
        }
        asm volatile("cp.async.commit_group;" ::: "memory");
    };

    issue(0, 0);
    issue(1, 1);

    for (int kt = 0; kt < NKT; kt++) {
        if (kt + 1 < NKT) asm volatile("cp.async.wait_group 1;" ::: "memory");
        else              asm volatile("cp.async.wait_group 0;" ::: "memory");
        __syncthreads();
        if (kt + 2 < NKT) issue(kt + 2, (kt + 2) % 3);

        int st = kt % 3;
        const uint4* A = (const uint4*)(sm + st * 8192);
        const uint2* B = (const uint2*)(sm + st * 8192 + 4096);
#pragma unroll
        for (int kc = 0; kc < 4; kc++) {
            uint4 a[2];
            uint2 b[8];
#pragma unroll
            for (int mt = 0; mt < 2; mt++)
                a[mt] = A[((wm * 2 + mt) * 4 + kc) * 32 + lane];
#pragma unroll
            for (int nt = 0; nt < 8; nt++)
                b[nt] = B[((wn * 8 + nt) * 4 + kc) * 32 + lane];
#pragma unroll
            for (int mt = 0; mt < 2; mt++)
#pragma unroll
                for (int nt = 0; nt < 8; nt++) {
                    float* c = acc + mt * 32 + nt * 4;
                    mma8(c[0], c[1], c[2], c[3],
                         a[mt].x, a[mt].y, a[mt].z, a[mt].w, b[nt].x, b[nt].y);
                }
        }
    }

    int r0 = rb * 128 + wm * 32 + (lane >> 2);
    int c0 = nblk * 128 + wn * 64 + 2 * (lane & 3);
#pragma unroll
    for (int mt = 0; mt < 2; mt++) {
#pragma unroll
        for (int nt = 0; nt < 8; nt++) {
            float* c = acc + mt * 32 + nt * 4;
            int col = c0 + nt * 8;
            float b0 = __ldg(ft_b + col), b1 = __ldg(ft_b + col + 1);
            float2 lo, hi;
            lo.x = fminf(fmaxf(c[0] + b0, 0.f), 1.f);
            lo.y = fminf(fmaxf(c[1] + b1, 0.f), 1.f);
            hi.x = fminf(fmaxf(c[2] + b0, 0.f), 1.f);
            hi.y = fminf(fmaxf(c[3] + b1, 0.f), 1.f);
            size_t base = (size_t)(r0 + mt * 16) * H1K + side * FTSZ + col;
            *(float2*)(g_comb + base) = lo;
            *(float2*)(g_comb + base + 8 * H1K) = hi;
        }
    }
}

// ---- head: CTA = 8 rows; f32x2 FMAs + multi-value butterfly reduction ----
__global__ __launch_bounds__(256) void k_head(
    const float* __restrict__ h1_w, const float* __restrict__ h1_b,
    const float* __restrict__ h2_w, const float* __restrict__ h2_b,
    const float* __restrict__ h3_w, const float* __restrict__ h3_b,
    float* __restrict__ out) {
    __shared__ float scomb[8 * 1024];
    __shared__ float sh1[8][33];
    __shared__ int sbk[8];
    int tid = threadIdx.x, w = tid >> 5, lane = tid & 31;
    int blk = blockIdx.x;

    {
        const float4* src = (const float4*)(g_comb + (size_t)blk * 8 * H1K);
        float4* dst = (float4*)scomb;
#pragma unroll
        for (int i = 0; i < 8; i++) dst[tid + i * 256] = __ldg(src + tid + i * 256);
        if (tid < 8) sbk[tid] = g_bucket[blk * 8 + tid];
    }
    __syncthreads();

    unsigned long long acc2[4][8];
#pragma unroll
    for (int o = 0; o < 4; o++)
#pragma unroll
        for (int r = 0; r < 8; r++) acc2[o][r] = 0ull;

    for (int b = 0; b < 8; b++) {
        unsigned rm = 0;
#pragma unroll
        for (int r = 0; r < 8; r++) if (sbk[r] == b) rm |= 1u << r;
        if (!rm) continue;
        const float4* wb = (const float4*)(h1_w + ((size_t)b * 32 + w * 4) * H1K);
#pragma unroll
        for (int c = 0; c < 4; c++) {
            unsigned long long wp[4][4];
#pragma unroll
            for (int o = 0; o < 4; o++) {
                float4 w0 = __ldg(wb + o * 256 + c * 64 + lane);
                float4 w1 = __ldg(wb + o * 256 + c * 64 + 32 + lane);
                wp[o][0] = *(unsigned long long*)&w0.x;
                wp[o][1] = *(unsigned long long*)&w0.z;
                wp[o][2] = *(unsigned long long*)&w1.x;
                wp[o][3] = *(unsigned long long*)&w1.z;
            }
#pragma unroll
            for (int r = 0; r < 8; r++) {
                if (!((rm >> r) & 1)) continue;
                float4 c0 = *(const float4*)(scomb + r * 1024 + c * 256 + lane * 4);
                float4 c1 = *(const float4*)(scomb + r * 1024 + c * 256 + 128 + lane * 4);
                unsigned long long cp0 = *(unsigned long long*)&c0.x;
                unsigned long long cp1 = *(unsigned long long*)&c0.z;
                unsigned long long cp2 = *(unsigned long long*)&c1.x;
                unsigned long long cp3 = *(unsigned long long*)&c1.z;
#pragma unroll
                for (int o = 0; o < 4; o++) {
                    fma2(acc2[o][r], cp0, wp[o][0]);
                    fma2(acc2[o][r], cp1, wp[o][1]);
                    fma2(acc2[o][r], cp2, wp[o][2]);
                    fma2(acc2[o][r], cp3, wp[o][3]);
                }
            }
        }
    }

    // multi-value butterfly: v[i] = value for (o=i&3, r=i>>2); after 5 stages,
    // lane l holds the full 32-lane sum of v[l].
    float v[32];
#pragma unroll
    for (int i = 0; i < 32; i++) {
        float2 p = *(float2*)&acc2[i & 3][i >> 2];
        v[i] = p.x + p.y;
    }
    {
        int n = 32;
#pragma unroll
        for (int off = 16; off >= 1; off >>= 1) {
            int half = n >> 1;
            bool hi = (lane & off) != 0;
#pragma unroll
            for (int i = 0; i < 16; i++) {
                if (i >= half) break;
                float a = v[i], b = v[i + half];
                float t = hi ? a : b;
                t = __shfl_xor_sync(0xffffffffu, t, off);
                v[i] = hi ? (b + t) : (a + t);
            }
            n = half;
        }
    }
    {
        int o = lane & 3, r = lane >> 2;
        int bk = sbk[r];
        float val = v[0] + __ldg(h1_b + bk * 32 + w * 4 + o);
        sh1[r][w * 4 + o] = fminf(fmaxf(val, 0.f), 1.f);
    }
    __syncthreads();

    int row = blk * 8 + w;
    int bk = sbk[w];
    const float4* w2 = (const float4*)(h2_w + (size_t)bk * 1024 + lane * 32);
    float a = 0.f;
#pragma unroll
    for (int rr = 0; rr < 8; rr++) {
        float4 wv = __ldg(w2 + rr);
        const float* h = &sh1[w][rr * 4];
        a += wv.x * h[0] + wv.y * h[1] + wv.z * h[2] + wv.w * h[3];
    }
    float h2v = fminf(fmaxf(a + __ldg(h2_b + bk * 32 + lane), 0.f), 1.f);
    float vv = __ldg(h3_w + bk * 32 + lane) * h2v;
#pragma unroll
    for (int off = 16; off; off >>= 1) vv += __shfl_xor_sync(0xffffffffu, vv, off);
    if (lane == 0) out[row] = vv + __ldg(h3_b + bk);
}

extern "C" void kernel_launch(void* const* d_in, const int* in_sizes, int n_in,
                              void* d_out, int out_size) {
    const float* x    = (const float*)d_in[0];
    const float* ft_w = (const float*)d_in[1];
    const float* ft_b = (const float*)d_in[2];
    const float* h1_w = (const float*)d_in[3];
    const float* h1_b = (const float*)d_in[4];
    const float* h2_w = (const float*)d_in[5];
    const float* h2_b = (const float*)d_in[6];
    const float* h3_w = (const float*)d_in[7];
    const float* h3_b = (const float*)d_in[8];
    float* out = (float*)d_out;

    cudaFuncSetAttribute(k_ft, cudaFuncAttributeMaxDynamicSharedMemorySize, 98304);

    k_bucket<<<BATCH / 8, 256>>>(x);
    k_prep_x<<<dim3(NKT, 512, 2), 256>>>(x);
    k_prep_wft<<<dim3(NKT, 4), 256>>>(ft_w);
    k_ft<<<dim3(8, 512), 256, 98304>>>(ft_b);
    k_head<<<BATCH / 8, 256>>>(h1_w, h1_b, h2_w, h2_b, h3_w, h3_b, out);
}